// round 10
// baseline (speedup 1.0000x reference)
#include <cuda_runtime.h>
#include <math.h>

#define HH 512
#define WW 512
#define NMAPS 160          // 32 * 5
#define STRIPS 8
#define RPS (HH / STRIPS)  // 64 rows per strip
#define NTH 128            // threads per block; each thread owns 4 columns
#define NEG_INF (-INFINITY)

// Partial top-3 per (map, strip) + completion counter (self-resetting).
__device__ float g_pval[NMAPS * STRIPS * 3];
__device__ int   g_pidx[NMAPS * STRIPS * 3];
__device__ int   g_ctr = 0;

__device__ __forceinline__ bool better(float av, int ai, float bv, int bi) {
    // lax.top_k ordering: value desc, index asc among ties
    return (av > bv) || ((av == bv) && (ai < bi));
}

// One block = one (map, row-strip). 128 threads = 4 warps; warp w owns columns
// [128w, 128w+128). Thread owns 4 columns (float4). Horizontal 5-max halo via
// warp shuffles; warp-edge lanes read a 2-col halo directly (L1-hot).
// Vertical 5-max via pair-max recurrence in registers. Rolling 4-deep row
// prefetch (per-thread MLP=4). NO smem / barriers in the mainloop.
__global__ void __launch_bounds__(NTH, 5) nms_topk_kernel(const float* __restrict__ hm,
                                                          float* __restrict__ out) {
    const int map   = blockIdx.x / STRIPS;
    const int strip = blockIdx.x % STRIPS;
    const int t     = threadIdx.x;
    const int lane  = t & 31;
    const int wb    = (t >> 5) * 128;   // warp's first column
    const int c0    = 4 * t;            // this thread's first column
    const float* base = hm + (long long)map * HH * WW;
    const int r0 = strip * RPS, r1 = r0 + RPS - 1;

    // Vertical state per column (x..w = cols c0..c0+3):
    //   hp = h of previous row; q1 = max(h[-1],h[-2]); q2 = max(h[-2],h[-3]);
    //   q3 = max(h[-3],h[-4]).  vm(row) = max(q3, q1, h)   (5-row window)
    float4 q1, q2, q3, hp;
    q1 = q2 = q3 = hp = make_float4(NEG_INF, NEG_INF, NEG_INF, NEG_INF);
    // Raw-value delay line: d2 = row lr-2 (center), d1 = row lr-1.
    float4 d1 = make_float4(0.f,0.f,0.f,0.f), d2 = d1;

    // Thread-local top-3 (sorted desc).
    float vt0 = NEG_INF, vt1 = NEG_INF, vt2 = NEG_INF;
    int   it0 = 0, it1 = 0, it2 = 0;

    // Row loader: clamped row, own float4 + warp-edge halo float2.
    auto ldrow = [&](int lr, float4& f, float2& hx) {
        int rc = min(max(lr, 0), HH - 1);
        const float* p = base + rc * WW;
        f = *(const float4*)(p + c0);
        if (lane == 0)
            hx = (wb > 0) ? *(const float2*)(p + wb - 2)
                          : make_float2(NEG_INF, NEG_INF);
        else if (lane == 31)
            hx = (wb + 128 < WW) ? *(const float2*)(p + wb + 128)
                                 : make_float2(NEG_INF, NEG_INF);
    };

    int ib = r0 * WW + c0;   // flat index of (er, c0), maintained incrementally

    auto ins = [&](float v, int idx) {
        if (v > vt2) {                       // rare path; strict > keeps ties stable
            if (v > vt0)      { vt2=vt1; it2=it1; vt1=vt0; it1=it0; vt0=v; it0=idx; }
            else if (v > vt1) { vt2=vt1; it2=it1; vt1=v;  it1=idx; }
            else              { vt2=v;  it2=idx; }
        }
    };

    // Process one loaded row lr; when do_ins, emit candidates for er = lr-2.
    auto process = [&](float4 x, float2 hx, int lr, bool do_ins) {
        float lm2 = __shfl_up_sync(0xffffffffu, x.z, 1);   // col c0-2
        float lm1 = __shfl_up_sync(0xffffffffu, x.w, 1);   // col c0-1
        float rp0 = __shfl_down_sync(0xffffffffu, x.x, 1); // col c0+4
        float rp1 = __shfl_down_sync(0xffffffffu, x.y, 1); // col c0+5
        if (lane == 0)  { lm2 = hx.x; lm1 = hx.y; }
        if (lane == 31) { rp0 = hx.x; rp1 = hx.y; }

        float a  = fmaxf(x.y, x.z);
        float h0 = fmaxf(fmaxf(lm2, lm1), fmaxf(x.x, a));
        float h1 = fmaxf(fmaxf(lm1, x.x), fmaxf(a, x.w));
        float h2 = fmaxf(fmaxf(x.x, a),  fmaxf(x.w, rp0));
        float h3 = fmaxf(fmaxf(a, x.w),  fmaxf(rp0, rp1));
        if ((unsigned)lr >= (unsigned)HH) { h0 = h1 = h2 = h3 = NEG_INF; }

        if (do_ins) {
            float vm0 = fmaxf(q3.x, fmaxf(q1.x, h0));
            float vm1 = fmaxf(q3.y, fmaxf(q1.y, h1));
            float vm2 = fmaxf(q3.z, fmaxf(q1.z, h2));
            float vm3 = fmaxf(q3.w, fmaxf(q1.w, h3));
            float v0c = (d2.x == vm0) ? d2.x : 0.0f;   // hm * (hm == pool)
            float v1c = (d2.y == vm1) ? d2.y : 0.0f;
            float v2c = (d2.z == vm2) ? d2.z : 0.0f;
            float v3c = (d2.w == vm3) ? d2.w : 0.0f;
            ins(v0c, ib);
            ins(v1c, ib + 1);
            ins(v2c, ib + 2);
            ins(v3c, ib + 3);
        }

        // Rotate state (uses above read pre-rotation values).
        q3 = q2; q2 = q1;
        q1 = make_float4(fmaxf(h0, hp.x), fmaxf(h1, hp.y),
                         fmaxf(h2, hp.z), fmaxf(h3, hp.w));
        hp = make_float4(h0, h1, h2, h3);
        d2 = d1; d1 = x;
    };

    // ---- Warm-up: rows r0-2 .. r0+1 fill the rings (no candidates) ----
    {
        float4 w0, w1, w2, w3; float2 e0, e1, e2, e3;
        ldrow(r0 - 2, w0, e0); ldrow(r0 - 1, w1, e1);
        ldrow(r0,     w2, e2); ldrow(r0 + 1, w3, e3);
        process(w0, e0, r0 - 2, false);
        process(w1, e1, r0 - 1, false);
        process(w2, e2, r0,     false);
        process(w3, e3, r0 + 1, false);
    }

    // ---- Main: rows r0+2 .. r1+2 (RPS = 64 rows), rolling 4-deep prefetch ----
    float4 f0, f1, f2, f3; float2 g0, g1, g2, g3;
    ldrow(r0 + 2, f0, g0);
    ldrow(r0 + 3, f1, g1);
    ldrow(r0 + 4, f2, g2);
    ldrow(r0 + 5, f3, g3);
    int lr = r0 + 2;
    for (int it = 0; it < RPS / 4; it++) {
        #pragma unroll
        for (int j = 0; j < 4; j++) {
            float4 x = f0; float2 hx = g0;
            f0 = f1; g0 = g1;
            f1 = f2; g1 = g2;
            f2 = f3; g2 = g3;
            ldrow(lr + 4, f3, g3);        // clamped; tail reloads row 511, harmless
            process(x, hx, lr, true);
            ib += WW;
            lr++;
        }
    }

    // ---- Block-wide top-3 merge (sorted-triple tree reduction) ----
    __shared__ float sv[NTH * 3];
    __shared__ int   si[NTH * 3];
    sv[t*3+0] = vt0; sv[t*3+1] = vt1; sv[t*3+2] = vt2;
    si[t*3+0] = it0; si[t*3+1] = it1; si[t*3+2] = it2;
    __syncthreads();
    for (int s = NTH / 2; s > 0; s >>= 1) {
        if (t < s) {
            float av[3], bv[3], ov[3]; int ai[3], bi[3], oi[3];
            #pragma unroll
            for (int k = 0; k < 3; k++) {
                av[k] = sv[t*3+k];       ai[k] = si[t*3+k];
                bv[k] = sv[(t+s)*3+k];   bi[k] = si[(t+s)*3+k];
            }
            int pa = 0, pb = 0;
            #pragma unroll
            for (int k = 0; k < 3; k++) {
                if (better(av[pa], ai[pa], bv[pb], bi[pb])) { ov[k]=av[pa]; oi[k]=ai[pa]; pa++; }
                else                                        { ov[k]=bv[pb]; oi[k]=bi[pb]; pb++; }
            }
            #pragma unroll
            for (int k = 0; k < 3; k++) { sv[t*3+k] = ov[k]; si[t*3+k] = oi[k]; }
        }
        __syncthreads();
    }

    __shared__ int s_last;
    if (t == 0) {
        int pb2 = blockIdx.x * 3;
        #pragma unroll
        for (int k = 0; k < 3; k++) { g_pval[pb2 + k] = sv[k]; g_pidx[pb2 + k] = si[k]; }
        __threadfence();
        int old = atomicAdd(&g_ctr, 1);
        s_last = (old == gridDim.x - 1) ? 1 : 0;
    }
    __syncthreads();

    // ---- Last block finalizes: merge strips, softmax, pack outputs ----
    // out[0:960) coords (bs,nc,3,2) | [960:1440) scores | [1440:1920) indices
    if (s_last) {
        for (int m = t; m < NMAPS; m += NTH) {
            float bv0 = NEG_INF, bv1 = NEG_INF, bv2 = NEG_INF;
            int   bi0 = 0, bi1 = 0, bi2 = 0;
            for (int s = 0; s < STRIPS; s++) {
                int pb = (m * STRIPS + s) * 3;
                #pragma unroll
                for (int k = 0; k < 3; k++) {
                    float v = __ldcg(&g_pval[pb + k]);
                    int   i = __ldcg(&g_pidx[pb + k]);
                    if (better(v, i, bv0, bi0))      { bv2=bv1; bi2=bi1; bv1=bv0; bi1=bi0; bv0=v; bi0=i; }
                    else if (better(v, i, bv1, bi1)) { bv2=bv1; bi2=bi1; bv1=v; bi1=i; }
                    else if (better(v, i, bv2, bi2)) { bv2=v; bi2=i; }
                }
            }
            float e1 = expf(bv1 - bv0);
            float e2 = expf(bv2 - bv0);
            float inv = 1.0f / (1.0f + e1 + e2);

            float* oc = out + m * 6;
            oc[0] = (float)(bi0 / WW); oc[1] = (float)(bi0 % WW);
            oc[2] = (float)(bi1 / WW); oc[3] = (float)(bi1 % WW);
            oc[4] = (float)(bi2 / WW); oc[5] = (float)(bi2 % WW);

            float* os = out + NMAPS * 6 + m * 3;
            os[0] = inv; os[1] = e1 * inv; os[2] = e2 * inv;

            float* oi = out + NMAPS * 9 + m * 3;
            oi[0] = (float)bi0; oi[1] = (float)bi1; oi[2] = (float)bi2;
        }
        if (t == 0) g_ctr = 0;   // self-reset for graph replay
    }
}

extern "C" void kernel_launch(void* const* d_in, const int* in_sizes, int n_in,
                              void* d_out, int out_size) {
    const float* hm = (const float*)d_in[0];
    float* out = (float*)d_out;
    nms_topk_kernel<<<NMAPS * STRIPS, NTH>>>(hm, out);
}